// round 2
// baseline (speedup 1.0000x reference)
#include <cuda_runtime.h>

// IRadon: filtered backprojection.
// Input  x: (4, 1, 363, 180) fp32, layout [n][0][s][a]
// Output:   (4, 1, 256, 256) fp32
//
// Stage 1 (filter_kernel): ramp filter along s == exact 363-tap symmetric
//   convolution h(0)=0.5, h(odd d)=-2/(pi d)^2, h(even)=0 (mathematically
//   identical to the reference's padded-FFT path). Emits a padded pair table
//   P[n][a][j] = (y[j-1], y[j]) with zero pads so backprojection needs no
//   bounds checks.
// Stage 2 (backproj_kernel): per output pixel, sum 180 angles of 1-D lerp
//   into the pair table; scale by pi/360.

#define N_BATCH   4
#define N_THETA   180
#define S_LEN     363          // GRID = ceil(sqrt(2)*256)
#define OUT_W     256
#define PAD_BEFORE 53          // crop offset: (256+107)//2 - 128
#define PAIR_STRIDE 365        // 363 samples + 1 zero pad each side
#define PI_D 3.14159265358979323846

// Scratch (allocation-free rule: __device__ globals).
__device__ float2 g_pairs[N_BATCH * N_THETA * PAIR_STRIDE];  // ~2.1 MB
__device__ float2 g_trig[N_THETA];

// ---------------------------------------------------------------------------
// Stage 1: ramp filter one (n, a) column per block. Also initializes the trig
// table (block (0,0)) — safe because only backproj (next kernel) reads it.
// ---------------------------------------------------------------------------
__global__ __launch_bounds__(384) void filter_kernel(const float* __restrict__ x)
{
    const int a = blockIdx.x;
    const int n = blockIdx.y;
    const int tid = threadIdx.x;

    if (blockIdx.x == 0 && blockIdx.y == 0 && tid < N_THETA) {
        double th = (double)tid * (PI_D / 180.0);
        g_trig[tid] = make_float2((float)cos(th), (float)sin(th));
    }

    // xs: logical indices [-361, 723] at phys offset +361  (size 1085 -> 1088)
    __shared__ float xs[1088];
    __shared__ float ys[368];   // ys[0]=0 pad, ys[1..363]=y[0..362], rest 0

    for (int i = tid; i < 1088; i += 384) xs[i] = 0.0f;
    for (int i = tid; i < 368;  i += 384) ys[i] = 0.0f;
    __syncthreads();

    if (tid < S_LEN)
        xs[361 + tid] = x[((size_t)n * S_LEN + tid) * N_THETA + a];
    __syncthreads();

    if (tid < S_LEN) {
        const float* xc = xs + tid;          // xc[361] == x[tid]
        float acc = 0.5f * xc[361];
        #pragma unroll
        for (int k = 0; k < 181; k++) {
            const int d = 2 * k + 1;
            const float w = (float)(-2.0 / (PI_D * PI_D * (double)d * (double)d));
            acc += (xc[361 - d] + xc[361 + d]) * w;
        }
        ys[1 + tid] = acc;
    }
    __syncthreads();

    float2* out = g_pairs + ((size_t)n * N_THETA + a) * PAIR_STRIDE;
    for (int j = tid; j < PAIR_STRIDE; j += 384)
        out[j] = make_float2(ys[j], ys[j + 1]);
}

// ---------------------------------------------------------------------------
// Stage 2: backprojection. Block = (32 x, 4 y-threads), 4 rows per thread
// (tile 32x16). pos = px*cos - py*sin + 181; pair-table lerp, no branches.
// ---------------------------------------------------------------------------
__global__ __launch_bounds__(128) void backproj_kernel(float* __restrict__ out)
{
    __shared__ float2 trig_s[N_THETA];
    const int tid = threadIdx.y * 32 + threadIdx.x;
    for (int t = tid; t < N_THETA; t += 128) trig_s[t] = g_trig[t];
    __syncthreads();

    const int n   = blockIdx.z;
    const int xg  = blockIdx.x * 32 + threadIdx.x;        // output col 0..255
    const int yg0 = blockIdx.y * 16 + threadIdx.y * 4;    // output row base

    // grid coordinates relative to center (grid index - 181), exact integers
    const float px = (float)(xg  + PAD_BEFORE - 181);
    const float py = (float)(yg0 + PAD_BEFORE - 181);

    float acc[4] = {0.f, 0.f, 0.f, 0.f};
    const float2* __restrict__ col = g_pairs + (size_t)n * (N_THETA * PAIR_STRIDE);

    #pragma unroll 4
    for (int a = 0; a < N_THETA; a++) {
        const float2 cs = trig_s[a];                       // (cos, sin)
        const float base = fmaf(-py, cs.y, 181.0f);
        const float pos0 = fmaf(px, cs.x, base);
        #pragma unroll
        for (int k = 0; k < 4; k++) {
            float pos = fmaf((float)(-k), cs.y, pos0);     // row y+k: py+k
            int   i   = __float2int_rd(pos);               // in [-1, 362]
            float f   = pos - (float)i;
            float2 v  = __ldg(&col[i + 1]);                // (y[i], y[i+1]), pads = 0
            acc[k] = fmaf(f, v.y - v.x, acc[k] + v.x);
        }
        col += PAIR_STRIDE;
    }

    const float SCALE = (float)(PI_D / 360.0);             // pi / (2*180)
    #pragma unroll
    for (int k = 0; k < 4; k++)
        out[((size_t)n * OUT_W + (yg0 + k)) * OUT_W + xg] = acc[k] * SCALE;
}

// ---------------------------------------------------------------------------
extern "C" void kernel_launch(void* const* d_in, const int* in_sizes, int n_in,
                              void* d_out, int out_size)
{
    const float* x = (const float*)d_in[0];
    float* out = (float*)d_out;

    filter_kernel<<<dim3(N_THETA, N_BATCH), 384>>>(x);
    backproj_kernel<<<dim3(OUT_W / 32, OUT_W / 16, N_BATCH), dim3(32, 4, 1)>>>(out);
}

// round 3
// speedup vs baseline: 1.4015x; 1.4015x over previous
#include <cuda_runtime.h>

// IRadon: filtered backprojection.
// Input  x: (4, 1, 363, 180) fp32, layout [n][0][s][a]
// Output:   (4, 1, 256, 256) fp32
//
// Stage 1 (filter_kernel): ramp filter along s == exact 363-tap symmetric
//   convolution h(0)=0.5, h(odd d)=-2/(pi d)^2, h(even)=0 (mathematically
//   identical to the reference's padded-FFT path). Emits a padded pair table
//   P[n][a][j] = (y[j-1], y[j]) with zero pads so backprojection needs no
//   bounds checks.
// Stage 2 (backproj_kernel): 1 output pixel per thread (R2: was 4 -> occupancy
//   21%, latency-bound). 180-angle loop, 4-way unrolled for per-warp MLP.

#define N_BATCH   4
#define N_THETA   180
#define S_LEN     363          // GRID = ceil(sqrt(2)*256)
#define OUT_W     256
#define PAD_BEFORE 53          // crop offset: (256+107)//2 - 128
#define PAIR_STRIDE 365        // 363 samples + 1 zero pad each side
#define PI_D 3.14159265358979323846

// Scratch (allocation-free rule: __device__ globals).
__device__ float2 g_pairs[N_BATCH * N_THETA * PAIR_STRIDE];  // ~2.1 MB
__device__ float2 g_trig[N_THETA];

// ---------------------------------------------------------------------------
// Stage 1: ramp filter one (n, a) column per block. Also initializes the trig
// table (block (0,0)) — safe because only backproj (next kernel) reads it.
// ---------------------------------------------------------------------------
__global__ __launch_bounds__(384) void filter_kernel(const float* __restrict__ x)
{
    const int a = blockIdx.x;
    const int n = blockIdx.y;
    const int tid = threadIdx.x;

    if (blockIdx.x == 0 && blockIdx.y == 0 && tid < N_THETA) {
        double th = (double)tid * (PI_D / 180.0);
        g_trig[tid] = make_float2((float)cos(th), (float)sin(th));
    }

    // xs: logical indices [-361, 723] at phys offset +361  (size 1085 -> 1088)
    __shared__ float xs[1088];
    __shared__ float ys[368];   // ys[0]=0 pad, ys[1..363]=y[0..362], rest 0

    for (int i = tid; i < 1088; i += 384) xs[i] = 0.0f;
    for (int i = tid; i < 368;  i += 384) ys[i] = 0.0f;
    __syncthreads();

    if (tid < S_LEN)
        xs[361 + tid] = x[((size_t)n * S_LEN + tid) * N_THETA + a];
    __syncthreads();

    if (tid < S_LEN) {
        const float* xc = xs + tid;          // xc[361] == x[tid]
        float acc = 0.5f * xc[361];
        #pragma unroll
        for (int k = 0; k < 181; k++) {
            const int d = 2 * k + 1;
            const float w = (float)(-2.0 / (PI_D * PI_D * (double)d * (double)d));
            acc += (xc[361 - d] + xc[361 + d]) * w;
        }
        ys[1 + tid] = acc;
    }
    __syncthreads();

    float2* out = g_pairs + ((size_t)n * N_THETA + a) * PAIR_STRIDE;
    for (int j = tid; j < PAIR_STRIDE; j += 384)
        out[j] = make_float2(ys[j], ys[j + 1]);
}

// ---------------------------------------------------------------------------
// Stage 2: backprojection, 1 pixel/thread.
// Block (32,8) = 256 threads, grid (8, 32, 4) = 1024 blocks -> 8192 warps
// (~55/SM) to cover the ~240-cycle L2 latency of the pair-table loads.
// pos = px*cos - py*sin + 181; branch-free pair-table lerp.
// ---------------------------------------------------------------------------
__global__ __launch_bounds__(256) void backproj_kernel(float* __restrict__ out)
{
    __shared__ float2 trig_s[N_THETA];
    const int tid = threadIdx.y * 32 + threadIdx.x;
    for (int t = tid; t < N_THETA; t += 256) trig_s[t] = g_trig[t];
    __syncthreads();

    const int n  = blockIdx.z;
    const int xg = blockIdx.x * 32 + threadIdx.x;        // output col 0..255
    const int yg = blockIdx.y * 8  + threadIdx.y;        // output row 0..255

    // grid coords relative to center: (idx + PAD_BEFORE) - 181 = idx - 128
    const float px = (float)(xg - 128);
    const float py = (float)(yg - 128);

    float acc = 0.0f;
    const float2* __restrict__ col = g_pairs + (size_t)n * (N_THETA * PAIR_STRIDE);

    #pragma unroll 4
    for (int a = 0; a < N_THETA; a++) {
        const float2 cs = trig_s[a];                      // (cos, sin)
        const float pos = fmaf(px, cs.x, fmaf(-py, cs.y, 181.0f));
        const int   i   = __float2int_rd(pos);            // in [-1, 362]
        const float f   = pos - (float)i;
        const float2 v  = __ldg(&col[i + 1]);             // (y[i], y[i+1]); pads = 0
        acc = fmaf(f, v.y - v.x, acc + v.x);
        col += PAIR_STRIDE;
    }

    const float SCALE = (float)(PI_D / 360.0);            // pi / (2*180)
    out[((size_t)n * OUT_W + yg) * OUT_W + xg] = acc * SCALE;
}

// ---------------------------------------------------------------------------
extern "C" void kernel_launch(void* const* d_in, const int* in_sizes, int n_in,
                              void* d_out, int out_size)
{
    const float* x = (const float*)d_in[0];
    float* out = (float*)d_out;

    filter_kernel<<<dim3(N_THETA, N_BATCH), 384>>>(x);
    backproj_kernel<<<dim3(OUT_W / 32, OUT_W / 8, N_BATCH), dim3(32, 8, 1)>>>(out);
}

// round 4
// speedup vs baseline: 1.6291x; 1.1623x over previous
#include <cuda_runtime.h>

// IRadon: filtered backprojection.
// Input  x: (4, 1, 363, 180) fp32, layout [n][0][s][a]
// Output:   (4, 1, 256, 256) fp32
//
// Stage 1 (filter_kernel): exact ramp filter h(0)=0.5, h(odd d)=-2/(pi d)^2,
//   h(even)=0. R3: parity-split samples, 4 outputs/thread, LDS.128-vectorized
//   taps with fully-unrolled compile-time immediate weights (FFMA-imm).
//   Emits padded pair table P[n][a][j] = (y[j-1], y[j]).
// Stage 2 (backproj_kernel): 1 pixel/thread; R3: 8x4 pixel tile per warp to
//   shrink the per-warp pair-table address span (L1 wavefront reduction).

#define N_BATCH   4
#define N_THETA   180
#define S_LEN     363          // GRID = ceil(sqrt(2)*256)
#define OUT_W     256
#define PAIR_STRIDE 365        // 363 samples + 1 zero pad each side
#define PI_D 3.14159265358979323846

// Scratch (allocation-free rule: __device__ globals).
__device__ float2 g_pairs[N_BATCH * N_THETA * PAIR_STRIDE];  // ~2.1 MB
__device__ float2 g_trig[N_THETA];

// ---------------------------------------------------------------------------
// Stage 1: ramp filter, one (n,a) column per block, 96 threads.
//
// Parity decomposition: output i only taps samples of opposite parity at odd
// distances d with weight w(d) = -2/(pi d)^2, plus 0.5*x[i].
//   even output 2m:   y = 0.5*x[2m]   + sum_t so[m+t]  * w(2t+1)
//   odd  output 2m+1: y = 0.5*x[2m+1] + sum_t se1[m+t] * w(2t+1)
// where so[j] = x[2j+1], se1[j] = x[2j+2] (shifted even array) -> identical
// code path for both groups, just a different base pointer.
// Thread handles centers m = 4u..4u+3; one float4 load feeds all 4 accs.
// ---------------------------------------------------------------------------
#define FPAD 184            // left guard (zeros) in parity arrays
#define FARR 560            // 184 + 364 + slack, 16B-aligned

__global__ __launch_bounds__(96) void filter_kernel(const float* __restrict__ x)
{
    const int a = blockIdx.x;
    const int n = blockIdx.y;
    const int tid = threadIdx.x;

    if (blockIdx.x == 0 && blockIdx.y == 0 && tid < 90) {
        double th0 = (double)(2 * tid) * (PI_D / 180.0);
        double th1 = (double)(2 * tid + 1) * (PI_D / 180.0);
        g_trig[2 * tid]     = make_float2((float)cos(th0), (float)sin(th0));
        g_trig[2 * tid + 1] = make_float2((float)cos(th1), (float)sin(th1));
    }

    __shared__ __align__(16) float so [FARR];  // so [FPAD+j] = x[2j+1], j in [0,180]
    __shared__ __align__(16) float se [FARR];  // se [FPAD+j] = x[2j],   j in [0,181]
    __shared__ __align__(16) float se1[FARR];  // se1[FPAD+j] = x[2j+2], j in [-1,180]
    __shared__ float ys[368];                  // ys[1+i] = y[i]; guards zero

    for (int i = tid; i < FARR; i += 96) { so[i] = 0.f; se[i] = 0.f; se1[i] = 0.f; }
    for (int i = tid; i < 368;  i += 96) ys[i] = 0.f;
    __syncthreads();

    for (int s = tid; s < S_LEN; s += 96) {
        float v = x[((size_t)n * S_LEN + s) * N_THETA + a];
        if (s & 1) so[FPAD + (s >> 1)] = v;
        else {
            se [FPAD + (s >> 1)]     = v;
            se1[FPAD + (s >> 1) - 1] = v;
        }
    }
    __syncthreads();

    // group A: tid 0..45  -> even outputs, arr = so,  self = se
    // group B: tid 48..93 -> odd  outputs, arr = se1, self = so
    const bool groupB = (tid >= 48);
    const int  u      = groupB ? (tid - 48) : tid;
    const bool active = (u < 46) && (tid < 94);

    if (active) {
        const float* __restrict__ arr  = groupB ? se1 : so;
        const float* __restrict__ self = groupB ? so  : se;
        const float* base = arr + FPAD + 4 * u;      // element j = 4u + T + e

        float acc0 = 0.5f * self[FPAD + 4 * u + 0];
        float acc1 = 0.5f * self[FPAD + 4 * u + 1];
        float acc2 = 0.5f * self[FPAD + 4 * u + 2];
        float acc3 = 0.5f * self[FPAD + 4 * u + 3];

        // t (relative tap) for center m=4u+k is T+e-k; covers [-187,183] ⊇ [-181,181].
        // Out-of-range t only multiplies zero-padded samples.
        #pragma unroll
        for (int it = 0; it < 92; it++) {
            const int T = -184 + 4 * it;
            const float4 V = *reinterpret_cast<const float4*>(base + T);
            #pragma unroll
            for (int e = 0; e < 4; e++) {
                const float ve = (e == 0) ? V.x : (e == 1) ? V.y : (e == 2) ? V.z : V.w;
                {   const int d = 2 * (T + e - 0) + 1;
                    acc0 = fmaf(ve, (float)(-2.0 / (PI_D * PI_D * (double)d * (double)d)), acc0); }
                {   const int d = 2 * (T + e - 1) + 1;
                    acc1 = fmaf(ve, (float)(-2.0 / (PI_D * PI_D * (double)d * (double)d)), acc1); }
                {   const int d = 2 * (T + e - 2) + 1;
                    acc2 = fmaf(ve, (float)(-2.0 / (PI_D * PI_D * (double)d * (double)d)), acc2); }
                {   const int d = 2 * (T + e - 3) + 1;
                    acc3 = fmaf(ve, (float)(-2.0 / (PI_D * PI_D * (double)d * (double)d)), acc3); }
            }
        }

        // write outputs: even group -> i = 2m; odd group -> i = 2m+1, m = 4u+k
        const int m0 = 4 * u;
        const int ib = groupB ? 1 : 0;
        const int lim = groupB ? 180 : 181;      // max valid m
        if (m0 + 0 <= lim) ys[1 + 2 * (m0 + 0) + ib] = acc0;
        if (m0 + 1 <= lim) ys[1 + 2 * (m0 + 1) + ib] = acc1;
        if (m0 + 2 <= lim) ys[1 + 2 * (m0 + 2) + ib] = acc2;
        if (m0 + 3 <= lim) ys[1 + 2 * (m0 + 3) + ib] = acc3;
    }
    __syncthreads();

    float2* out = g_pairs + ((size_t)n * N_THETA + a) * PAIR_STRIDE;
    for (int j = tid; j < PAIR_STRIDE; j += 96)
        out[j] = make_float2(ys[j], ys[j + 1]);
}

// ---------------------------------------------------------------------------
// Stage 2: backprojection, 1 pixel/thread, 8x4 tile per warp.
// Block 256 threads = 2x4 warps = 16x16 pixel tile; grid (16,16,4).
// pos = px*cos - py*sin + 181; branch-free pair-table lerp.
// ---------------------------------------------------------------------------
__global__ __launch_bounds__(256) void backproj_kernel(float* __restrict__ out)
{
    __shared__ float2 trig_s[N_THETA];
    const int tid = threadIdx.x;
    for (int t = tid; t < N_THETA; t += 256) trig_s[t] = g_trig[t];
    __syncthreads();

    const int warp = tid >> 5, lane = tid & 31;
    const int lx = lane & 7,  ly = lane >> 3;      // 8x4 lane tile
    const int wx = warp & 1,  wy = warp >> 1;      // 2x4 warp grid

    const int n  = blockIdx.z;
    const int xg = blockIdx.x * 16 + wx * 8 + lx;  // output col 0..255
    const int yg = blockIdx.y * 16 + wy * 4 + ly;  // output row 0..255

    // grid coords relative to center: (idx + 53) - 181 = idx - 128
    const float px = (float)(xg - 128);
    const float py = (float)(yg - 128);

    float acc = 0.0f;
    const float2* __restrict__ col = g_pairs + (size_t)n * (N_THETA * PAIR_STRIDE);

    #pragma unroll 4
    for (int a = 0; a < N_THETA; a++) {
        const float2 cs = trig_s[a];                      // (cos, sin)
        const float pos = fmaf(px, cs.x, fmaf(-py, cs.y, 181.0f));
        const int   i   = __float2int_rd(pos);            // in [-1, 362]
        const float f   = pos - (float)i;
        const float2 v  = __ldg(&col[i + 1]);             // (y[i], y[i+1]); pads = 0
        acc = fmaf(f, v.y - v.x, acc + v.x);
        col += PAIR_STRIDE;
    }

    const float SCALE = (float)(PI_D / 360.0);            // pi / (2*180)
    out[((size_t)n * OUT_W + yg) * OUT_W + xg] = acc * SCALE;
}

// ---------------------------------------------------------------------------
extern "C" void kernel_launch(void* const* d_in, const int* in_sizes, int n_in,
                              void* d_out, int out_size)
{
    const float* x = (const float*)d_in[0];
    float* out = (float*)d_out;

    filter_kernel<<<dim3(N_THETA, N_BATCH), 96>>>(x);
    backproj_kernel<<<dim3(OUT_W / 16, OUT_W / 16, N_BATCH), dim3(256, 1, 1)>>>(out);
}

// round 5
// speedup vs baseline: 1.7183x; 1.0548x over previous
#include <cuda_runtime.h>
#include <math.h>

// IRadon: filtered backprojection.
// Input  x: (4, 1, 363, 180) fp32, layout [n][0][s][a]
// Output:   (4, 1, 256, 256) fp32
//
// Stage 1 (filter_kernel): exact ramp filter h(0)=0.5, h(odd d)=-2/(pi d)^2,
//   h(even)=0. Parity-split samples, 4 outputs/thread, LDS.128-vectorized
//   taps with fully-unrolled compile-time immediate weights (FFMA-imm).
//   R4: emits slope-form pair table P[n][a][j] = (y[j-1], y[j]-y[j-1]).
// Stage 2 (backproj_kernel): 1 pixel/thread. R4: trig delivered via
//   __grid_constant__ kernel argument (host-computed) -> ULDC on the uniform
//   pipe instead of LDS; slope-form lerp saves one FADD per angle.

#define N_BATCH   4
#define N_THETA   180
#define S_LEN     363          // GRID = ceil(sqrt(2)*256)
#define OUT_W     256
#define PAIR_STRIDE 365        // 363 samples + 1 zero pad each side
#define PI_D 3.14159265358979323846

// Scratch (allocation-free rule: __device__ globals).
__device__ float2 g_pairs[N_BATCH * N_THETA * PAIR_STRIDE];  // ~2.1 MB

struct TrigArgs { float2 cs[N_THETA]; };   // 1440 B, by-value kernel arg

// ---------------------------------------------------------------------------
// Stage 1: ramp filter, one (n,a) column per block, 96 threads.
// Parity decomposition: output i taps opposite-parity samples at odd
// distances d with weight w(d) = -2/(pi d)^2, plus 0.5*x[i].
// ---------------------------------------------------------------------------
#define FPAD 184            // left guard (zeros) in parity arrays
#define FARR 560            // 184 + 364 + slack, 16B-aligned

__global__ __launch_bounds__(96) void filter_kernel(const float* __restrict__ x)
{
    const int a = blockIdx.x;
    const int n = blockIdx.y;
    const int tid = threadIdx.x;

    __shared__ __align__(16) float so [FARR];  // so [FPAD+j] = x[2j+1]
    __shared__ __align__(16) float se [FARR];  // se [FPAD+j] = x[2j]
    __shared__ __align__(16) float se1[FARR];  // se1[FPAD+j] = x[2j+2]
    __shared__ float ys[368];                  // ys[1+i] = y[i]; guards zero

    for (int i = tid; i < FARR; i += 96) { so[i] = 0.f; se[i] = 0.f; se1[i] = 0.f; }
    for (int i = tid; i < 368;  i += 96) ys[i] = 0.f;
    __syncthreads();

    for (int s = tid; s < S_LEN; s += 96) {
        float v = x[((size_t)n * S_LEN + s) * N_THETA + a];
        if (s & 1) so[FPAD + (s >> 1)] = v;
        else {
            se [FPAD + (s >> 1)]     = v;
            se1[FPAD + (s >> 1) - 1] = v;
        }
    }
    __syncthreads();

    // group A: tid 0..45  -> even outputs, arr = so,  self = se
    // group B: tid 48..93 -> odd  outputs, arr = se1, self = so
    const bool groupB = (tid >= 48);
    const int  u      = groupB ? (tid - 48) : tid;
    const bool active = (u < 46) && (tid < 94);

    if (active) {
        const float* __restrict__ arr  = groupB ? se1 : so;
        const float* __restrict__ self = groupB ? so  : se;
        const float* base = arr + FPAD + 4 * u;

        float acc0 = 0.5f * self[FPAD + 4 * u + 0];
        float acc1 = 0.5f * self[FPAD + 4 * u + 1];
        float acc2 = 0.5f * self[FPAD + 4 * u + 2];
        float acc3 = 0.5f * self[FPAD + 4 * u + 3];

        #pragma unroll
        for (int it = 0; it < 92; it++) {
            const int T = -184 + 4 * it;
            const float4 V = *reinterpret_cast<const float4*>(base + T);
            #pragma unroll
            for (int e = 0; e < 4; e++) {
                const float ve = (e == 0) ? V.x : (e == 1) ? V.y : (e == 2) ? V.z : V.w;
                {   const int d = 2 * (T + e - 0) + 1;
                    acc0 = fmaf(ve, (float)(-2.0 / (PI_D * PI_D * (double)d * (double)d)), acc0); }
                {   const int d = 2 * (T + e - 1) + 1;
                    acc1 = fmaf(ve, (float)(-2.0 / (PI_D * PI_D * (double)d * (double)d)), acc1); }
                {   const int d = 2 * (T + e - 2) + 1;
                    acc2 = fmaf(ve, (float)(-2.0 / (PI_D * PI_D * (double)d * (double)d)), acc2); }
                {   const int d = 2 * (T + e - 3) + 1;
                    acc3 = fmaf(ve, (float)(-2.0 / (PI_D * PI_D * (double)d * (double)d)), acc3); }
            }
        }

        const int m0 = 4 * u;
        const int ib = groupB ? 1 : 0;
        const int lim = groupB ? 180 : 181;
        if (m0 + 0 <= lim) ys[1 + 2 * (m0 + 0) + ib] = acc0;
        if (m0 + 1 <= lim) ys[1 + 2 * (m0 + 1) + ib] = acc1;
        if (m0 + 2 <= lim) ys[1 + 2 * (m0 + 2) + ib] = acc2;
        if (m0 + 3 <= lim) ys[1 + 2 * (m0 + 3) + ib] = acc3;
    }
    __syncthreads();

    // slope-form pair table: (y[j-1], y[j]-y[j-1]); zero guards give the
    // reference's boundary-masked lerp automatically.
    float2* out = g_pairs + ((size_t)n * N_THETA + a) * PAIR_STRIDE;
    for (int j = tid; j < PAIR_STRIDE; j += 96)
        out[j] = make_float2(ys[j], ys[j + 1] - ys[j]);
}

// ---------------------------------------------------------------------------
// Stage 2: backprojection, 1 pixel/thread, block (32,8), grid (8,32,4).
// pos = px*cos - py*sin + 181; slope-form branch-free lerp.
// ---------------------------------------------------------------------------
__global__ __launch_bounds__(256) void backproj_kernel(
    float* __restrict__ out, const __grid_constant__ TrigArgs trig)
{
    const int n  = blockIdx.z;
    const int xg = blockIdx.x * 32 + threadIdx.x;        // output col 0..255
    const int yg = blockIdx.y * 8  + threadIdx.y;        // output row 0..255

    // grid coords relative to center: (idx + 53) - 181 = idx - 128
    const float px = (float)(xg - 128);
    const float py = (float)(yg - 128);

    float acc = 0.0f;
    const float2* __restrict__ col = g_pairs + (size_t)n * (N_THETA * PAIR_STRIDE);

    #pragma unroll 4
    for (int a = 0; a < N_THETA; a++) {
        const float2 cs = trig.cs[a];                     // ULDC (const bank)
        const float pos = fmaf(px, cs.x, fmaf(-py, cs.y, 181.0f));
        const int   i   = __float2int_rd(pos);            // in [-1, 362]
        const float f   = pos - (float)i;
        const float2 v  = __ldg(&col[i + 1]);             // (y[i], y[i+1]-y[i])
        acc = fmaf(f, v.y, acc + v.x);
        col += PAIR_STRIDE;
    }

    const float SCALE = (float)(PI_D / 360.0);            // pi / (2*180)
    out[((size_t)n * OUT_W + yg) * OUT_W + xg] = acc * SCALE;
}

// ---------------------------------------------------------------------------
extern "C" void kernel_launch(void* const* d_in, const int* in_sizes, int n_in,
                              void* d_out, int out_size)
{
    const float* x = (const float*)d_in[0];
    float* out = (float*)d_out;

    TrigArgs trig;
    for (int a = 0; a < N_THETA; a++) {
        double th = (double)a * (PI_D / 180.0);
        trig.cs[a] = make_float2((float)cos(th), (float)sin(th));
    }

    filter_kernel<<<dim3(N_THETA, N_BATCH), 96>>>(x);
    backproj_kernel<<<dim3(OUT_W / 32, OUT_W / 8, N_BATCH), dim3(32, 8, 1)>>>(out, trig);
}